// round 5
// baseline (speedup 1.0000x reference)
#include <cuda_runtime.h>
#include <cuda_fp16.h>
#include <stdint.h>

#define BB    128
#define TT    512
#define HH    256
#define LL    6
#define INW   128
#define FOURH 1024
#define NC    16
#define GRIDB (LL*NC)      // 96
#define NTH   512
#define KMAX  512
#define SMEM_BYTES (192*(2*HH+8)*2)   // (64 w-rows + 128 act-rows) * 520 halfs * 2B = 199680

// ---------------- persistent device state ----------------
__device__ __align__(256) __half d_wpack[(size_t)LL*FOURH*KMAX];  // fp16 [Wih|Whh], gate-packed rows
__device__ __align__(256) float  d_bpack[LL*FOURH];               // b_ih + b_hh, packed order
__device__ __align__(256) __half d_xh[(size_t)BB*TT*INW];         // x in fp16
__device__ __align__(256) __half d_hring[LL*4*BB*HH];             // 4-slot h ring per layer
__device__ unsigned g_arrive[LL];                                 // monotonic per-layer progress

__device__ __forceinline__ int hring_off(int l, int slot, int b, int k){
  return ((l*4 + slot)*BB + b)*HH + k;
}

// ---------------- prep kernels ----------------
// Packed row p in 64-row CTA chunk: p = gate*16 + jj  (R3 layout, validated)
__global__ void prep_pack(const float* __restrict__ w_ih0,
                          const float* __restrict__ w_ih,
                          const float* __restrict__ w_hh,
                          const float* __restrict__ b_ih,
                          const float* __restrict__ b_hh){
  long long idx = (long long)blockIdx.x*blockDim.x + threadIdx.x;
  if (idx >= (long long)LL*FOURH*KMAX) return;
  int k = (int)(idx % KMAX);
  int p = (int)((idx / KMAX) % FOURH);
  int l = (int)(idx / ((long long)KMAX*FOURH));
  int cid = p >> 6, rr = p & 63, gate = rr >> 4, jj = rr & 15;
  int srow = gate*HH + cid*16 + jj;       // original 4H row (i,f,g,o order)
  int din  = (l == 0) ? INW : HH;
  float v = 0.f;
  if (k < din)            v = (l == 0) ? w_ih0[srow*INW + k]
                                       : w_ih[((size_t)(l-1)*FOURH + srow)*HH + k];
  else if (k < din + HH)  v = w_hh[((size_t)l*FOURH + srow)*HH + (k - din)];
  d_wpack[idx] = __float2half(v);
  if (k == 0) d_bpack[l*FOURH + p] = b_ih[l*FOURH + srow] + b_hh[l*FOURH + srow];
}

__global__ void prep_x(const float* __restrict__ x){
  long long i = (long long)blockIdx.x*blockDim.x + threadIdx.x;
  if (i < (long long)BB*TT*INW) d_xh[i] = __float2half(x[i]);
}

__global__ void prep_init(const float* __restrict__ h0){
  int i = blockIdx.x*blockDim.x + threadIdx.x;
  if (i < LL*BB*HH){
    int l = i/(BB*HH), rem = i%(BB*HH);
    d_hring[hring_off(l, 0, rem/HH, rem%HH)] = __float2half(h0[i]);
  }
  if (i == 0){
    #pragma unroll
    for (int l = 0; l < LL; l++) g_arrive[l] = 0u;
  }
}

// ---------------- low-level helpers ----------------
__device__ __forceinline__ unsigned smem_u32(const void* p){
  unsigned a;
  asm("{ .reg .u64 t; cvta.to.shared.u64 t, %1; cvt.u32.u64 %0, t; }" : "=r"(a) : "l"(p));
  return a;
}
__device__ __forceinline__ void cp_async16(uint32_t dst, const void* src){
  asm volatile("cp.async.cg.shared.global [%0], [%1], 16;" :: "r"(dst), "l"(src));
}
__device__ __forceinline__ void cp_commit_wait(){
  asm volatile("cp.async.commit_group;");
  asm volatile("cp.async.wait_group 0;" ::: "memory");
}
__device__ __forceinline__ void ldsm_x4(unsigned addr, unsigned& r0, unsigned& r1,
                                        unsigned& r2, unsigned& r3){
  asm volatile("ldmatrix.sync.aligned.m8n8.x4.shared.b16 {%0,%1,%2,%3}, [%4];\n"
               : "=r"(r0), "=r"(r1), "=r"(r2), "=r"(r3) : "r"(addr));
}
__device__ __forceinline__ void mma_16816(float d[4], const unsigned a[4], const unsigned b0,
                                          const unsigned b1){
  asm volatile("mma.sync.aligned.m16n8k16.row.col.f32.f16.f16.f32 "
               "{%0,%1,%2,%3}, {%4,%5,%6,%7}, {%8,%9}, {%0,%1,%2,%3};\n"
               : "+f"(d[0]), "+f"(d[1]), "+f"(d[2]), "+f"(d[3])
               : "r"(a[0]), "r"(a[1]), "r"(a[2]), "r"(a[3]), "r"(b0), "r"(b1));
}
__device__ __forceinline__ float tanh_fast(float x){
  float r; asm("tanh.approx.f32 %0, %1;" : "=f"(r) : "f"(x)); return r;
}
__device__ __forceinline__ float sig_fast(float x){
  return fmaf(tanh_fast(0.5f*x), 0.5f, 0.5f);
}
__device__ __forceinline__ void wait_ge(unsigned* p, unsigned target){
  unsigned v;
  #pragma unroll 1
  do {
    asm volatile("ld.acquire.gpu.global.u32 %0, [%1];" : "=r"(v) : "l"(p) : "memory");
  } while (v < target);
}
__device__ __forceinline__ void arrive_release(unsigned* p){
  asm volatile("red.release.gpu.global.add.u32 [%0], %1;" :: "l"(p), "r"(1u) : "memory");
}
__device__ __forceinline__ void st_cg_u32(void* p, unsigned v){
  asm volatile("st.global.cg.u32 [%0], %1;" :: "l"(p), "r"(v) : "memory");
}

// ---------------- per-layer persistent worker ----------------
// 16 warps = Mw4 x Nw2 x Ks2. Warp (wm,wn,ks) computes the partial GEMM over
// K-slice ks for rows [wm*32, wm*32+32) and (via the gate-grouped B mapping)
// all four gate groups of h-columns [wn*8, wn*8+8). ks=1 stores partials to a
// 32KB fp32 smem tile (aliasing the A buffer); ks=0 adds them and runs the
// gate epilogue with cell state in registers.
template<int KL, int DINA>
__device__ __forceinline__ void run_layer(const int l, const int cid,
                                          const float* __restrict__ c0,
                                          float* __restrict__ out, char* smem_raw)
{
  constexpr int SI  = KL + 8;                // padded row stride in halfs
  constexpr int KSH = KL / 2;                // K per ks-slice (192 or 256)
  constexpr int NIT = KSH / 16;              // k16 iterations per slice
  constexpr int CRh = KL / 8;                // 16B chunks per A row
  __half* ws  = (__half*)smem_raw;           // [64][SI]  weights (persistent)
  __half* inp = ws + 64*SI;                  // [128][SI] activations
  float*  gsh = (float*)inp;                 // [128][65] ks=1 partials (alias)
  const int tid = threadIdx.x;

  // ---- load this CTA's 64 packed weight rows into smem (once) ----
  {
    const __half* src = d_wpack + ((size_t)(l*FOURH + cid*64))*KMAX;
    for (int v = tid; v < 64*CRh; v += NTH){
      int r = v / CRh, kk = (v - r*CRh)*8;
      *(uint4*)(ws + r*SI + kk) = *(const uint4*)(src + (size_t)r*KMAX + kk);
    }
  }

  // ---- thread mapping ----
  const int w = tid >> 5, lane = tid & 31;
  const int ks = w >> 3, w8 = w & 7;
  const int wm = w8 & 3, wn = w8 >> 2;
  const int q = lane >> 3, rs = lane & 7;
  const int gid = lane >> 2, ct = lane & 3;

  // A: m16k16 tiles, rows wm*32 + {0..15} (+16 for second M tile)
  const unsigned aBase0 = smem_u32(inp + (wm*32 + rs + ((q&1)<<3))*SI + ((q>>1)<<3));
  const unsigned aBase1 = aBase0 + (unsigned)(32*SI);            // +16 rows (bytes)
  // B: gate-grouped: rows g*16 + wn*8 + {0..7}; bBase0 -> gates 0,1; +64*SI -> gates 2,3
  const unsigned bBase0 = smem_u32(ws + (wn*8 + rs + ((q>>1)<<4))*SI + ((q&1)<<3));
  const unsigned bBase1 = bBase0 + (unsigned)(64*SI);

  // ---- per-thread gate cell ownership (ks==0 warps do the epilogue) ----
  float bias[4][2];
  #pragma unroll
  for (int g = 0; g < 4; g++)
    #pragma unroll
    for (int cc = 0; cc < 2; cc++)
      bias[g][cc] = d_bpack[l*FOURH + cid*64 + g*16 + wn*8 + ct*2 + cc];

  float creg[8];
  #pragma unroll
  for (int mt = 0; mt < 2; mt++)
    #pragma unroll
    for (int rr = 0; rr < 2; rr++)
      #pragma unroll
      for (int cc = 0; cc < 2; cc++){
        int r  = wm*32 + mt*16 + gid + rr*8;
        int cg = cid*16 + wn*8 + ct*2 + cc;
        creg[mt*4 + rr*2 + cc] = c0[(l*BB + r)*HH + cg];
      }

  const uint32_t inpB = smem_u32(inp);

  for (int t = 0; t < TT; t++){
    // ---- dependency waits (monotonic counters; acquire) ----
    if (tid == 0){
      if (l > 0)               wait_ge(&g_arrive[l-1], 16u*(unsigned)(t+1));    // below done t
      if (t > 0)               wait_ge(&g_arrive[l],   16u*(unsigned)t);        // peers done t-1
      if (l < LL-1 && t >= 3)  wait_ge(&g_arrive[l+1], 16u*(unsigned)(t-2));    // ring WAR safe
    }
    __syncthreads();

    // ---- stage A tile [128][KL] = [below | own h_{t-1}] via cp.async.cg ----
    {
      const __half* hA = d_hring + hring_off((l>0)?(l-1):0, (t+1)&3, 0, 0);
      const __half* hB = d_hring + hring_off(l, t&3, 0, 0);
      for (int v = tid; v < 128*CRh; v += NTH){
        int r = v / CRh, kc = (v - r*CRh)*8;
        const __half* src;
        if (DINA == INW)
          src = (kc < INW) ? (d_xh + ((size_t)r*TT + t)*INW + kc)
                           : (hB + r*HH + (kc - INW));
        else
          src = (kc < HH)  ? (hA + r*HH + kc)
                           : (hB + r*HH + (kc - HH));
        cp_async16(inpB + (uint32_t)(r*SI + kc)*2u, src);
      }
      cp_commit_wait();
    }
    __syncthreads();

    // ---- partial GEMM over this warp's K-slice ----
    float acc[2][4][4];
    #pragma unroll
    for (int i = 0; i < 2; i++)
      #pragma unroll
      for (int j = 0; j < 4; j++)
        #pragma unroll
        for (int kx = 0; kx < 4; kx++) acc[i][j][kx] = 0.f;

    #pragma unroll
    for (int ki = 0; ki < NIT; ki++){
      const unsigned kofs = (unsigned)((ks*KSH + ki*16)*2);
      unsigned a0[4], a1[4], b01[4], b23[4];
      ldsm_x4(aBase0 + kofs, a0[0], a0[1], a0[2], a0[3]);
      ldsm_x4(aBase1 + kofs, a1[0], a1[1], a1[2], a1[3]);
      ldsm_x4(bBase0 + kofs, b01[0], b01[1], b01[2], b01[3]);
      ldsm_x4(bBase1 + kofs, b23[0], b23[1], b23[2], b23[3]);
      mma_16816(acc[0][0], a0, b01[0], b01[1]);   // gate i
      mma_16816(acc[1][0], a1, b01[0], b01[1]);
      mma_16816(acc[0][1], a0, b01[2], b01[3]);   // gate f
      mma_16816(acc[1][1], a1, b01[2], b01[3]);
      mma_16816(acc[0][2], a0, b23[0], b23[1]);   // gate g
      mma_16816(acc[1][2], a1, b23[0], b23[1]);
      mma_16816(acc[0][3], a0, b23[2], b23[3]);   // gate o
      mma_16816(acc[1][3], a1, b23[2], b23[3]);
    }
    __syncthreads();                 // all ldsm reads done -> safe to alias gsh over inp

    // ---- ks=1: store partials ----
    if (ks == 1){
      #pragma unroll
      for (int mt = 0; mt < 2; mt++)
        #pragma unroll
        for (int g = 0; g < 4; g++)
          #pragma unroll
          for (int rr = 0; rr < 2; rr++){
            int row = wm*32 + mt*16 + gid + rr*8;
            int col = g*16 + wn*8 + ct*2;
            gsh[row*65 + col    ] = acc[mt][g][rr*2    ];
            gsh[row*65 + col + 1] = acc[mt][g][rr*2 + 1];
          }
    }
    __syncthreads();

    // ---- ks=0: reduce + gates in registers; h -> L2 ring ----
    if (ks == 0){
      __half* hslot = d_hring + hring_off(l, (t+1)&3, 0, 0);
      #pragma unroll
      for (int mt = 0; mt < 2; mt++)
        #pragma unroll
        for (int rr = 0; rr < 2; rr++){
          int row = wm*32 + mt*16 + gid + rr*8;
          float hv[2];
          #pragma unroll
          for (int cc = 0; cc < 2; cc++){
            int e  = rr*2 + cc;
            int ci = mt*4 + rr*2 + cc;
            int cb = wn*8 + ct*2 + cc;
            float gi = acc[mt][0][e] + gsh[row*65 +      cb] + bias[0][cc];
            float gf = acc[mt][1][e] + gsh[row*65 + 16 + cb] + bias[1][cc];
            float gg = acc[mt][2][e] + gsh[row*65 + 32 + cb] + bias[2][cc];
            float go = acc[mt][3][e] + gsh[row*65 + 48 + cb] + bias[3][cc];
            float c  = sig_fast(gf)*creg[ci] + sig_fast(gi)*tanh_fast(gg);
            creg[ci] = c;
            hv[cc]   = sig_fast(go)*tanh_fast(c);
          }
          int cg0 = cid*16 + wn*8 + ct*2;
          __half2 h2 = __floats2half2_rn(hv[0], hv[1]);
          st_cg_u32(hslot + row*HH + cg0, *(unsigned*)&h2);
          if (t == TT-1){
            out[(l*BB + row)*HH + cg0    ] = hv[0];
            out[(l*BB + row)*HH + cg0 + 1] = hv[1];
          }
        }
    }
    __syncthreads();
    if (tid == 0) arrive_release(&g_arrive[l]);
  }
}

__global__ void __launch_bounds__(NTH, 1)
lstm_persist(const float* __restrict__ c0, float* __restrict__ out)
{
  extern __shared__ __align__(16) char smem_raw[];
  const int l = blockIdx.x >> 4, cid = blockIdx.x & 15;
  if (l == 0) run_layer<INW + HH, INW>(0, cid, c0, out, smem_raw);
  else        run_layer<2*HH,    HH >(l, cid, c0, out, smem_raw);
}

// ---------------- launch ----------------
extern "C" void kernel_launch(void* const* d_in, const int* in_sizes, int n_in,
                              void* d_out, int out_size){
  const float* x     = (const float*)d_in[0];
  const float* h0    = (const float*)d_in[1];
  const float* c0    = (const float*)d_in[2];
  const float* w_ih0 = (const float*)d_in[3];
  const float* w_ih  = (const float*)d_in[4];
  const float* w_hh  = (const float*)d_in[5];
  const float* b_ih  = (const float*)d_in[6];
  const float* b_hh  = (const float*)d_in[7];
  float* out = (float*)d_out;

  cudaFuncSetAttribute(lstm_persist, cudaFuncAttributeMaxDynamicSharedMemorySize, SMEM_BYTES);

  prep_pack<<<(LL*FOURH*KMAX + 255)/256, 256>>>(w_ih0, w_ih, w_hh, b_ih, b_hh);
  prep_x   <<<(BB*TT*INW    + 255)/256, 256>>>(x);
  prep_init<<<(LL*BB*HH     + 255)/256, 256>>>(h0);
  lstm_persist<<<GRIDB, NTH, SMEM_BYTES>>>(c0, out);
}

// round 6
// speedup vs baseline: 1.0777x; 1.0777x over previous
#include <cuda_runtime.h>
#include <cuda_fp16.h>
#include <stdint.h>

#define BB    128
#define TT    512
#define HH    256
#define LL    6
#define INW   128
#define FOURH 1024
#define NC    16
#define GRIDB (LL*NC)      // 96
#define NTH   256
#define KMAX  512
// smem (l>0): ws 64*520*2 + own 128*264*2 + inp 128*264*2 = 201728 bytes
#define SMEM_BYTES (64*(256+HH+8)*2 + 128*(HH+8)*2 + 128*(HH+8)*2)

// ---------------- persistent device state ----------------
__device__ __align__(256) __half d_wpack[(size_t)LL*FOURH*KMAX];  // rows: [Whh(256) | Wih(din)]
__device__ __align__(256) float  d_bpack[LL*FOURH];
__device__ __align__(256) __half d_xh[(size_t)BB*TT*INW];
__device__ __align__(256) __half d_hring[LL*4*BB*HH];             // 4-slot h ring per layer
__device__ unsigned g_arrive[LL];

__device__ __forceinline__ int hring_off(int l, int slot, int b, int k){
  return ((l*4 + slot)*BB + b)*HH + k;
}

// ---------------- prep kernels ----------------
// Packed row p in 64-row CTA chunk: p = gate*16 + jj (gate-grouped, R3-validated).
// Row columns: [0,256) = Whh[srow], [256,256+din) = Wih[srow].
__global__ void prep_pack(const float* __restrict__ w_ih0,
                          const float* __restrict__ w_ih,
                          const float* __restrict__ w_hh,
                          const float* __restrict__ b_ih,
                          const float* __restrict__ b_hh){
  long long idx = (long long)blockIdx.x*blockDim.x + threadIdx.x;
  if (idx >= (long long)LL*FOURH*KMAX) return;
  int k = (int)(idx % KMAX);
  int p = (int)((idx / KMAX) % FOURH);
  int l = (int)(idx / ((long long)KMAX*FOURH));
  int cid = p >> 6, rr = p & 63, gate = rr >> 4, jj = rr & 15;
  int srow = gate*HH + cid*16 + jj;       // original 4H row (i,f,g,o order)
  int din  = (l == 0) ? INW : HH;
  float v = 0.f;
  if (k < HH)             v = w_hh[((size_t)l*FOURH + srow)*HH + k];
  else if (k < HH + din)  v = (l == 0) ? w_ih0[srow*INW + (k - HH)]
                                       : w_ih[((size_t)(l-1)*FOURH + srow)*HH + (k - HH)];
  d_wpack[idx] = __float2half(v);
  if (k == 0) d_bpack[l*FOURH + p] = b_ih[l*FOURH + srow] + b_hh[l*FOURH + srow];
}

__global__ void prep_x(const float* __restrict__ x){
  long long i = (long long)blockIdx.x*blockDim.x + threadIdx.x;
  if (i < (long long)BB*TT*INW) d_xh[i] = __float2half(x[i]);
}

__global__ void prep_init(const float* __restrict__ h0){
  int i = blockIdx.x*blockDim.x + threadIdx.x;
  if (i < LL*BB*HH){
    int l = i/(BB*HH), rem = i%(BB*HH);
    d_hring[hring_off(l, 0, rem/HH, rem%HH)] = __float2half(h0[i]);
  }
  if (i == 0){
    #pragma unroll
    for (int l = 0; l < LL; l++) g_arrive[l] = 0u;
  }
}

// ---------------- low-level helpers ----------------
__device__ __forceinline__ unsigned smem_u32(const void* p){
  unsigned a;
  asm("{ .reg .u64 t; cvta.to.shared.u64 t, %1; cvt.u32.u64 %0, t; }" : "=r"(a) : "l"(p));
  return a;
}
__device__ __forceinline__ void cp_async16(uint32_t dst, const void* src){
  asm volatile("cp.async.cg.shared.global [%0], [%1], 16;" :: "r"(dst), "l"(src));
}
__device__ __forceinline__ void cp_commit_wait(){
  asm volatile("cp.async.commit_group;");
  asm volatile("cp.async.wait_group 0;" ::: "memory");
}
__device__ __forceinline__ void ldsm_x4(unsigned addr, unsigned& r0, unsigned& r1,
                                        unsigned& r2, unsigned& r3){
  asm volatile("ldmatrix.sync.aligned.m8n8.x4.shared.b16 {%0,%1,%2,%3}, [%4];\n"
               : "=r"(r0), "=r"(r1), "=r"(r2), "=r"(r3) : "r"(addr));
}
__device__ __forceinline__ void mma_16816(float d[4], const unsigned a[4], const unsigned b0,
                                          const unsigned b1){
  asm volatile("mma.sync.aligned.m16n8k16.row.col.f32.f16.f16.f32 "
               "{%0,%1,%2,%3}, {%4,%5,%6,%7}, {%8,%9}, {%0,%1,%2,%3};\n"
               : "+f"(d[0]), "+f"(d[1]), "+f"(d[2]), "+f"(d[3])
               : "r"(a[0]), "r"(a[1]), "r"(a[2]), "r"(a[3]), "r"(b0), "r"(b1));
}
__device__ __forceinline__ float tanh_fast(float x){
  float r; asm("tanh.approx.f32 %0, %1;" : "=f"(r) : "f"(x)); return r;
}
__device__ __forceinline__ float sig_fast(float x){
  return fmaf(tanh_fast(0.5f*x), 0.5f, 0.5f);
}
__device__ __forceinline__ void wait_ge(unsigned* p, unsigned target){
  unsigned v;
  #pragma unroll 1
  do {
    asm volatile("ld.acquire.gpu.global.u32 %0, [%1];" : "=r"(v) : "l"(p) : "memory");
  } while (v < target);
}
__device__ __forceinline__ void arrive_release(unsigned* p){
  asm volatile("red.release.gpu.global.add.u32 [%0], %1;" :: "l"(p), "r"(1u) : "memory");
}
__device__ __forceinline__ void st_cg_u32(void* p, unsigned v){
  asm volatile("st.global.cg.u32 [%0], %1;" :: "l"(p), "r"(v) : "memory");
}

// one k16 slab of the 8-warp (Mw4 x Nw2) gate-grouped GEMM
__device__ __forceinline__ void gemm_k16(float accA[4][4], float accB[4][4],
                                         unsigned aB0, unsigned aB1,
                                         unsigned bB0, unsigned bB1, unsigned kofs){
  unsigned a0[4], a1[4], b01[4], b23[4];
  ldsm_x4(aB0 + kofs, a0[0], a0[1], a0[2], a0[3]);
  ldsm_x4(aB1 + kofs, a1[0], a1[1], a1[2], a1[3]);
  ldsm_x4(bB0 + kofs, b01[0], b01[1], b01[2], b01[3]);
  ldsm_x4(bB1 + kofs, b23[0], b23[1], b23[2], b23[3]);
  mma_16816(accA[0], a0, b01[0], b01[1]);   // gate i
  mma_16816(accB[0], a1, b01[0], b01[1]);
  mma_16816(accA[1], a0, b01[2], b01[3]);   // gate f
  mma_16816(accB[1], a1, b01[2], b01[3]);
  mma_16816(accA[2], a0, b23[0], b23[1]);   // gate g
  mma_16816(accB[2], a1, b23[0], b23[1]);
  mma_16816(accA[3], a0, b23[2], b23[3]);   // gate o
  mma_16816(accB[3], a1, b23[2], b23[3]);
}

// ---------------- per-layer persistent worker ----------------
// 8 warps = Mw4 x Nw2 (R3 mapping). Two accumulators: accR (recurrent K=256,
// on the critical path) and accI (input K=DINA, computed one step AHEAD right
// after release, off the critical path).
template<int DINA>
__device__ __forceinline__ void run_layer(const int l, const int cid,
                                          const float* __restrict__ c0,
                                          float* __restrict__ out, char* smem_raw)
{
  constexpr int SIW = 256 + DINA + 8;        // weight row stride (halfs)
  constexpr int SIA = HH + 8;                // own-h tile stride
  constexpr int SII = DINA + 8;              // input tile stride
  constexpr int NI  = DINA / 16;             // input-GEMM k16 iters
  __half* ws  = (__half*)smem_raw;           // [64][SIW]
  __half* own = ws  + 64*SIW;                // [128][SIA]
  __half* inp = own + 128*SIA;               // [128][SII]
  const int tid = threadIdx.x;

  // ---- load this CTA's 64 packed weight rows (once) ----
  {
    const __half* src = d_wpack + ((size_t)(l*FOURH + cid*64))*KMAX;
    constexpr int CRW = (256 + DINA)/8;
    for (int v = tid; v < 64*CRW; v += NTH){
      int r = v / CRW, kk = (v - r*CRW)*8;
      *(uint4*)(ws + r*SIW + kk) = *(const uint4*)(src + (size_t)r*KMAX + kk);
    }
  }

  // ---- thread mapping (R3-validated) ----
  const int w = tid >> 5, lane = tid & 31;
  const int wm = w & 3, wn = w >> 2;
  const int q = lane >> 3, rs = lane & 7;
  const int gid = lane >> 2, ct = lane & 3;

  const unsigned aR0 = smem_u32(own + (wm*32 + rs + ((q&1)<<3))*SIA + ((q>>1)<<3));
  const unsigned aR1 = aR0 + (unsigned)(32*SIA);
  const unsigned aI0 = smem_u32(inp + (wm*32 + rs + ((q&1)<<3))*SII + ((q>>1)<<3));
  const unsigned aI1 = aI0 + (unsigned)(32*SII);
  const unsigned bR0 = smem_u32(ws + (wn*8 + rs + ((q>>1)<<4))*SIW + ((q&1)<<3));
  const unsigned bR1 = bR0 + (unsigned)(64*SIW);
  const unsigned bI0 = bR0 + (unsigned)(256*2);   // +256 half columns
  const unsigned bI1 = bR1 + (unsigned)(256*2);

  // ---- per-thread gate cell ownership ----
  float bias[4][2];
  #pragma unroll
  for (int g = 0; g < 4; g++)
    #pragma unroll
    for (int cc = 0; cc < 2; cc++)
      bias[g][cc] = d_bpack[l*FOURH + cid*64 + g*16 + wn*8 + ct*2 + cc];

  float creg[8];
  #pragma unroll
  for (int mt = 0; mt < 2; mt++)
    #pragma unroll
    for (int rr = 0; rr < 2; rr++)
      #pragma unroll
      for (int cc = 0; cc < 2; cc++){
        int r  = wm*32 + mt*16 + gid + rr*8;
        int cg = cid*16 + wn*8 + ct*2 + cc;
        creg[mt*4 + rr*2 + cc] = c0[(l*BB + r)*HH + cg];
      }

  const uint32_t ownB = smem_u32(own);
  const uint32_t inpB = smem_u32(inp);

  float accI[2][4][4];

  // ---- input phase for step tt: stage below input, GEMM K=DINA -> accI ----
  auto input_phase = [&](int tt){
    if (tid == 0 && l > 0) wait_ge(&g_arrive[l-1], 16u*(unsigned)(tt+1));
    __syncthreads();
    if (DINA == INW){   // layer 0: x
      for (int v = tid; v < 128*(INW/8); v += NTH){
        int r = v >> 4, kk = (v & 15)*8;
        cp_async16(inpB + (uint32_t)(r*SII + kk)*2u,
                   d_xh + ((size_t)r*TT + tt)*INW + kk);
      }
    } else {
      const __half* hb = d_hring + hring_off(l-1, (tt+1)&3, 0, 0);
      for (int v = tid; v < 128*(HH/8); v += NTH){
        int r = v >> 5, kk = (v & 31)*8;
        cp_async16(inpB + (uint32_t)(r*SII + kk)*2u, hb + r*HH + kk);
      }
    }
    cp_commit_wait();
    __syncthreads();
    #pragma unroll
    for (int i = 0; i < 2; i++)
      #pragma unroll
      for (int j = 0; j < 4; j++)
        #pragma unroll
        for (int kx = 0; kx < 4; kx++) accI[i][j][kx] = 0.f;
    #pragma unroll
    for (int ki = 0; ki < NI; ki++)
      gemm_k16(accI[0], accI[1], aI0, aI1, bI0, bI1, (unsigned)(ki*32));
  };

  input_phase(0);   // preamble: accI for step 0

  for (int t = 0; t < TT; t++){
    // ---- critical-path waits ----
    if (tid == 0){
      if (t > 0)               wait_ge(&g_arrive[l],   16u*(unsigned)t);
      if (l < LL-1 && t >= 3)  wait_ge(&g_arrive[l+1], 16u*(unsigned)(t-2));
    }
    __syncthreads();

    // ---- stage own h_{t-1} (slot t&3) ----
    {
      const __half* hs = d_hring + hring_off(l, t&3, 0, 0);
      for (int v = tid; v < 128*(HH/8); v += NTH){
        int r = v >> 5, kk = (v & 31)*8;
        cp_async16(ownB + (uint32_t)(r*SIA + kk)*2u, hs + r*HH + kk);
      }
      cp_commit_wait();
    }
    __syncthreads();

    // ---- recurrent GEMM K=256 -> accR ----
    float accR[2][4][4];
    #pragma unroll
    for (int i = 0; i < 2; i++)
      #pragma unroll
      for (int j = 0; j < 4; j++)
        #pragma unroll
        for (int kx = 0; kx < 4; kx++) accR[i][j][kx] = 0.f;
    #pragma unroll
    for (int ki = 0; ki < 16; ki++)
      gemm_k16(accR[0], accR[1], aR0, aR1, bR0, bR1, (unsigned)(ki*32));

    // ---- gates = accR + accI + bias; c in regs; h -> L2 ring ----
    {
      __half* hslot = d_hring + hring_off(l, (t+1)&3, 0, 0);
      #pragma unroll
      for (int mt = 0; mt < 2; mt++)
        #pragma unroll
        for (int rr = 0; rr < 2; rr++){
          int row = wm*32 + mt*16 + gid + rr*8;
          float hv[2];
          #pragma unroll
          for (int cc = 0; cc < 2; cc++){
            int e  = rr*2 + cc;
            int ci = mt*4 + rr*2 + cc;
            float gi = accR[mt][0][e] + accI[mt][0][e] + bias[0][cc];
            float gf = accR[mt][1][e] + accI[mt][1][e] + bias[1][cc];
            float gg = accR[mt][2][e] + accI[mt][2][e] + bias[2][cc];
            float go = accR[mt][3][e] + accI[mt][3][e] + bias[3][cc];
            float c  = sig_fast(gf)*creg[ci] + sig_fast(gi)*tanh_fast(gg);
            creg[ci] = c;
            hv[cc]   = sig_fast(go)*tanh_fast(c);
          }
          int cg0 = cid*16 + wn*8 + ct*2;
          __half2 h2 = __floats2half2_rn(hv[0], hv[1]);
          st_cg_u32(hslot + row*HH + cg0, *(unsigned*)&h2);
          if (t == TT-1){
            out[(l*BB + row)*HH + cg0    ] = hv[0];
            out[(l*BB + row)*HH + cg0 + 1] = hv[1];
          }
        }
    }
    __syncthreads();
    if (tid == 0) arrive_release(&g_arrive[l]);

    // ---- off-critical-path: input phase for step t+1 ----
    if (t < TT-1) input_phase(t+1);
  }
}

__global__ void __launch_bounds__(NTH, 1)
lstm_persist(const float* __restrict__ c0, float* __restrict__ out)
{
  extern __shared__ __align__(16) char smem_raw[];
  const int l = blockIdx.x >> 4, cid = blockIdx.x & 15;
  if (l == 0) run_layer<INW>(0, cid, c0, out, smem_raw);
  else        run_layer<HH >(l, cid, c0, out, smem_raw);
}

// ---------------- launch ----------------
extern "C" void kernel_launch(void* const* d_in, const int* in_sizes, int n_in,
                              void* d_out, int out_size){
  const float* x     = (const float*)d_in[0];
  const float* h0    = (const float*)d_in[1];
  const float* c0    = (const float*)d_in[2];
  const float* w_ih0 = (const float*)d_in[3];
  const float* w_ih  = (const float*)d_in[4];
  const float* w_hh  = (const float*)d_in[5];
  const float* b_ih  = (const float*)d_in[6];
  const float* b_hh  = (const float*)d_in[7];
  float* out = (float*)d_out;

  cudaFuncSetAttribute(lstm_persist, cudaFuncAttributeMaxDynamicSharedMemorySize, SMEM_BYTES);

  prep_pack<<<(LL*FOURH*KMAX + 255)/256, 256>>>(w_ih0, w_ih, w_hh, b_ih, b_hh);
  prep_x   <<<(BB*TT*INW    + 255)/256, 256>>>(x);
  prep_init<<<(LL*BB*HH     + 255)/256, 256>>>(h0);
  lstm_persist<<<GRIDB, NTH, SMEM_BYTES>>>(c0, out);
}

// round 7
// speedup vs baseline: 1.1861x; 1.1006x over previous
#include <cuda_runtime.h>
#include <cuda_fp16.h>
#include <stdint.h>

#define BB    128
#define TT    512
#define HH    256
#define LL    6
#define INW   128
#define FOURH 1024
#define NC    16
#define GRIDB (LL*NC)      // 96
#define NTH   256
#define KMAX  512
// ws 64*520*2 + own 128*264*2 + inph 64*264*2 + gbuf 128*68*4 = 202752
#define SMEM_BYTES 202752

// ---------------- persistent device state ----------------
__device__ __align__(256) __half d_wpack[(size_t)LL*FOURH*KMAX];  // rows: [Whh(256) | Wih(din)]
__device__ __align__(256) float  d_bpack[LL*FOURH];
__device__ __align__(256) __half d_xh[(size_t)BB*TT*INW];
__device__ __align__(256) __half d_hring[LL*4*BB*HH];             // 4-slot h ring per layer
__device__ unsigned g_arrive[LL];

__device__ __forceinline__ int hring_off(int l, int slot, int b, int k){
  return ((l*4 + slot)*BB + b)*HH + k;
}

// ---------------- prep kernels ----------------
// Packed row p in 64-row CTA chunk: p = gate*16 + jj. Cols: [0,256)=Whh, [256,256+din)=Wih.
__global__ void prep_pack(const float* __restrict__ w_ih0,
                          const float* __restrict__ w_ih,
                          const float* __restrict__ w_hh,
                          const float* __restrict__ b_ih,
                          const float* __restrict__ b_hh){
  long long idx = (long long)blockIdx.x*blockDim.x + threadIdx.x;
  if (idx >= (long long)LL*FOURH*KMAX) return;
  int k = (int)(idx % KMAX);
  int p = (int)((idx / KMAX) % FOURH);
  int l = (int)(idx / ((long long)KMAX*FOURH));
  int cid = p >> 6, rr = p & 63, gate = rr >> 4, jj = rr & 15;
  int srow = gate*HH + cid*16 + jj;
  int din  = (l == 0) ? INW : HH;
  float v = 0.f;
  if (k < HH)             v = w_hh[((size_t)l*FOURH + srow)*HH + k];
  else if (k < HH + din)  v = (l == 0) ? w_ih0[srow*INW + (k - HH)]
                                       : w_ih[((size_t)(l-1)*FOURH + srow)*HH + (k - HH)];
  d_wpack[idx] = __float2half(v);
  if (k == 0) d_bpack[l*FOURH + p] = b_ih[l*FOURH + srow] + b_hh[l*FOURH + srow];
}

__global__ void prep_x(const float* __restrict__ x){
  long long i = (long long)blockIdx.x*blockDim.x + threadIdx.x;
  if (i < (long long)BB*TT*INW) d_xh[i] = __float2half(x[i]);
}

__global__ void prep_init(const float* __restrict__ h0){
  int i = blockIdx.x*blockDim.x + threadIdx.x;
  if (i < LL*BB*HH){
    int l = i/(BB*HH), rem = i%(BB*HH);
    d_hring[hring_off(l, 0, rem/HH, rem%HH)] = __float2half(h0[i]);
  }
  if (i == 0){
    #pragma unroll
    for (int l = 0; l < LL; l++) g_arrive[l] = 0u;
  }
}

// ---------------- low-level helpers ----------------
__device__ __forceinline__ unsigned smem_u32(const void* p){
  unsigned a;
  asm("{ .reg .u64 t; cvta.to.shared.u64 t, %1; cvt.u32.u64 %0, t; }" : "=r"(a) : "l"(p));
  return a;
}
__device__ __forceinline__ void cp_async16(uint32_t dst, const void* src){
  asm volatile("cp.async.cg.shared.global [%0], [%1], 16;" :: "r"(dst), "l"(src));
}
__device__ __forceinline__ void cp_commit_wait(){
  asm volatile("cp.async.commit_group;");
  asm volatile("cp.async.wait_group 0;" ::: "memory");
}
__device__ __forceinline__ void bar_sync(int id, int cnt){
  asm volatile("bar.sync %0, %1;" :: "r"(id), "r"(cnt) : "memory");
}
__device__ __forceinline__ void ldsm_x4(unsigned addr, unsigned& r0, unsigned& r1,
                                        unsigned& r2, unsigned& r3){
  asm volatile("ldmatrix.sync.aligned.m8n8.x4.shared.b16 {%0,%1,%2,%3}, [%4];\n"
               : "=r"(r0), "=r"(r1), "=r"(r2), "=r"(r3) : "r"(addr));
}
__device__ __forceinline__ void mma_16816(float d[4], const unsigned a[4], const unsigned b0,
                                          const unsigned b1){
  asm volatile("mma.sync.aligned.m16n8k16.row.col.f32.f16.f16.f32 "
               "{%0,%1,%2,%3}, {%4,%5,%6,%7}, {%8,%9}, {%0,%1,%2,%3};\n"
               : "+f"(d[0]), "+f"(d[1]), "+f"(d[2]), "+f"(d[3])
               : "r"(a[0]), "r"(a[1]), "r"(a[2]), "r"(a[3]), "r"(b0), "r"(b1));
}
__device__ __forceinline__ float tanh_fast(float x){
  float r; asm("tanh.approx.f32 %0, %1;" : "=f"(r) : "f"(x)); return r;
}
__device__ __forceinline__ float sig_fast(float x){
  return fmaf(tanh_fast(0.5f*x), 0.5f, 0.5f);
}
__device__ __forceinline__ void wait_ge(unsigned* p, unsigned target){
  unsigned v;
  #pragma unroll 1
  do {
    asm volatile("ld.acquire.gpu.global.u32 %0, [%1];" : "=r"(v) : "l"(p) : "memory");
  } while (v < target);
}
__device__ __forceinline__ void arrive_release(unsigned* p){
  asm volatile("red.release.gpu.global.add.u32 [%0], %1;" :: "l"(p), "r"(1u) : "memory");
}
__device__ __forceinline__ void st_cg_u32(void* p, unsigned v){
  asm volatile("st.global.cg.u32 [%0], %1;" :: "l"(p), "r"(v) : "memory");
}
__device__ __forceinline__ void sts128(uint32_t addr, float a, float b, float c, float d){
  asm volatile("st.shared.v4.b32 [%0], {%1,%2,%3,%4};"
               :: "r"(addr), "r"(__float_as_uint(a)), "r"(__float_as_uint(b)),
                  "r"(__float_as_uint(c)), "r"(__float_as_uint(d)) : "memory");
}
__device__ __forceinline__ void lds128(uint32_t addr, float& a, float& b, float& c, float& d){
  unsigned u0,u1,u2,u3;
  asm volatile("ld.shared.v4.b32 {%0,%1,%2,%3}, [%4];"
               : "=r"(u0), "=r"(u1), "=r"(u2), "=r"(u3) : "r"(addr));
  a=__uint_as_float(u0); b=__uint_as_float(u1); c=__uint_as_float(u2); d=__uint_as_float(u3);
}

// 8 n-tile B fragments from 4 ldsm.x4 at packed rows {0,8,32,40} (+16 inside each)
// nt order: ldsm0 -> nt0,nt2 ; ldsm1 -> nt1,nt3 ; ldsm2 -> nt4,nt6 ; ldsm3 -> nt5,nt7

// ---------------- per-layer persistent worker ----------------
template<int DINA>
__device__ __forceinline__ void run_layer(const int l, const int cid,
                                          const float* __restrict__ c0,
                                          float* __restrict__ out, char* smem_raw)
{
  constexpr int SIW = KMAX + 8;              // 520
  constexpr int SIA = HH + 8;                // 264
  constexpr int SII = DINA + 8;
  constexpr int NI  = DINA/16;               // input k16 iters (per full K)
  constexpr int CH  = DINA/8;                // 16B chunks per input row
  __half* ws   = (__half*)smem_raw;          // [64][520]
  __half* own  = ws  + 64*SIW;               // [128][264]
  __half* inph = own + 128*SIA;              // [64][SII]  (half-tile, interleaved rows)
  float*  gbuf = (float*)(inph + 64*SII);    // [128][68]  per-REC-thread dump
  const int tid = threadIdx.x;

  // ---- stage weights (once, all 256 threads) ----
  {
    const __half* src = d_wpack + ((size_t)(l*FOURH + cid*64))*KMAX;
    for (int v = tid; v < 64*64; v += NTH){
      int r = v >> 6, kk = (v & 63)*8;
      *(uint4*)(ws + r*SIW + kk) = *(const uint4*)(src + (size_t)r*KMAX + kk);
    }
  }

  const int w = tid >> 5, lane = tid & 31;
  const int q = lane >> 3, rs = lane & 7;
  const int gid = lane >> 2, ct = lane & 3;

  // B fragment bases (Whh region cols [0,256))
  unsigned bX[4];
  {
    const int Xs[4] = {0, 8, 32, 40};
    #pragma unroll
    for (int i = 0; i < 4; i++)
      bX[i] = smem_u32(ws + (Xs[i] + rs + ((q>>1)<<4))*SIW + ((q&1)<<3));
  }

  __syncthreads();

  if (w < 4){
    // ================= REC warps: critical path =================
    const unsigned aB0 = smem_u32(own + (w*32 + rs + ((q&1)<<3))*SIA + ((q>>1)<<3));
    const unsigned aB1 = aB0 + (unsigned)(32*SIA);     // +16 rows in bytes
    const uint32_t ownB = smem_u32(own);
    const uint32_t gdst = smem_u32(gbuf) + (unsigned)tid*272u;

    for (int t = 0; t < TT; t++){
      if (tid == 0){
        if (t > 0)               wait_ge(&g_arrive[l],   16u*(unsigned)t);
        if (l < LL-1 && t >= 3)  wait_ge(&g_arrive[l+1], 16u*(unsigned)(t-2));
      }
      bar_sync(4, 128);

      // stage own h_{t-1} (slot t&3), 64KB
      {
        const __half* hs = d_hring + hring_off(l, t&3, 0, 0);
        for (int v = tid; v < 4096; v += 128){
          int r = v >> 5, kk = (v & 31)*8;
          cp_async16(ownB + (uint32_t)(r*SIA + kk)*2u, hs + r*HH + kk);
        }
        cp_commit_wait();
      }
      bar_sync(4, 128);

      // recurrent GEMM K=256: acc[mt][nt][e]
      float acc[2][8][4];
      #pragma unroll
      for (int i = 0; i < 2; i++)
        #pragma unroll
        for (int j = 0; j < 8; j++)
          #pragma unroll
          for (int e = 0; e < 4; e++) acc[i][j][e] = 0.f;

      #pragma unroll
      for (int ki = 0; ki < 16; ki++){
        const unsigned kofs = (unsigned)(ki*32);
        unsigned a0[4], a1[4], b0[4], b1[4], b2[4], b3[4];
        ldsm_x4(aB0 + kofs, a0[0], a0[1], a0[2], a0[3]);
        ldsm_x4(aB1 + kofs, a1[0], a1[1], a1[2], a1[3]);
        ldsm_x4(bX[0] + kofs, b0[0], b0[1], b0[2], b0[3]);
        ldsm_x4(bX[1] + kofs, b1[0], b1[1], b1[2], b1[3]);
        ldsm_x4(bX[2] + kofs, b2[0], b2[1], b2[2], b2[3]);
        ldsm_x4(bX[3] + kofs, b3[0], b3[1], b3[2], b3[3]);
        #pragma unroll
        for (int mt = 0; mt < 2; mt++){
          const unsigned* a = mt ? a1 : a0;
          mma_16816(acc[mt][0], a, b0[0], b0[1]);
          mma_16816(acc[mt][1], a, b1[0], b1[1]);
          mma_16816(acc[mt][2], a, b0[2], b0[3]);
          mma_16816(acc[mt][3], a, b1[2], b1[3]);
          mma_16816(acc[mt][4], a, b2[0], b2[1]);
          mma_16816(acc[mt][5], a, b3[0], b3[1]);
          mma_16816(acc[mt][6], a, b2[2], b2[3]);
          mma_16816(acc[mt][7], a, b3[2], b3[3]);
        }
      }
      bar_sync(1, NTH);

      // dump 64 floats (flat, vectorized)
      #pragma unroll
      for (int mt = 0; mt < 2; mt++)
        #pragma unroll
        for (int nt = 0; nt < 8; nt++)
          sts128(gdst + (unsigned)((mt*8 + nt)*16),
                 acc[mt][nt][0], acc[mt][nt][1], acc[mt][nt][2], acc[mt][nt][3]);
      bar_sync(2, NTH);
    }
  } else {
    // ================= INP warps: input pipeline + epilogue =================
    const int wi = w - 4;
    const unsigned aI = smem_u32(inph + (wi*16 + rs + ((q&1)<<3))*SII + ((q>>1)<<3));
    unsigned bI[4];
    #pragma unroll
    for (int i = 0; i < 4; i++) bI[i] = bX[i] + 512u;   // Wih cols start at half 256
    const uint32_t inpB = smem_u32(inph);
    const uint32_t gsrc = smem_u32(gbuf) + (unsigned)(tid - 128)*272u;

    float bias[16];
    #pragma unroll
    for (int g = 0; g < 4; g++)
      #pragma unroll
      for (int jh = 0; jh < 2; jh++)
        #pragma unroll
        for (int cc = 0; cc < 2; cc++)
          bias[g*4 + jh*2 + cc] = d_bpack[l*FOURH + cid*64 + g*16 + jh*8 + ct*2 + cc];

    float creg[16];
    #pragma unroll
    for (int mt = 0; mt < 2; mt++)
      #pragma unroll
      for (int rr = 0; rr < 2; rr++)
        #pragma unroll
        for (int jh = 0; jh < 2; jh++)
          #pragma unroll
          for (int cc = 0; cc < 2; cc++){
            int row = wi*32 + mt*16 + gid + rr*8;
            int col = cid*16 + jh*8 + ct*2 + cc;
            creg[mt*8 + rr*4 + jh*2 + cc] = c0[(l*BB + row)*HH + col];
          }

    for (int t = 0; t < TT; t++){
      if (tid == 128 && l > 0) wait_ge(&g_arrive[l-1], 16u*(unsigned)(t+1));

      float accI[2][8][4];
      #pragma unroll
      for (int h = 0; h < 2; h++){
        bar_sync(3, 128);
        // stage half h: buffer row br -> global row (br>>4)*32 + h*16 + (br&15)
        for (int v = tid - 128; v < 64*CH; v += 128){
          int br = v / CH, kk = (v - br*CH)*8;
          int gr = ((br >> 4) << 5) + h*16 + (br & 15);
          const __half* src = (DINA == INW)
            ? d_xh + ((size_t)gr*TT + t)*INW + kk
            : d_hring + hring_off(l-1, (t+1)&3, gr, kk);
          cp_async16(inpB + (uint32_t)(br*SII + kk)*2u, src);
        }
        cp_commit_wait();
        bar_sync(3, 128);
        // input GEMM K=DINA for this half
        #pragma unroll
        for (int j = 0; j < 8; j++)
          #pragma unroll
          for (int e = 0; e < 4; e++) accI[h][j][e] = 0.f;
        #pragma unroll
        for (int ki = 0; ki < NI; ki++){
          const unsigned kofs = (unsigned)(ki*32);
          unsigned a[4], b0[4], b1[4], b2[4], b3[4];
          ldsm_x4(aI + kofs, a[0], a[1], a[2], a[3]);
          ldsm_x4(bI[0] + kofs, b0[0], b0[1], b0[2], b0[3]);
          ldsm_x4(bI[1] + kofs, b1[0], b1[1], b1[2], b1[3]);
          ldsm_x4(bI[2] + kofs, b2[0], b2[1], b2[2], b2[3]);
          ldsm_x4(bI[3] + kofs, b3[0], b3[1], b3[2], b3[3]);
          mma_16816(accI[h][0], a, b0[0], b0[1]);
          mma_16816(accI[h][1], a, b1[0], b1[1]);
          mma_16816(accI[h][2], a, b0[2], b0[3]);
          mma_16816(accI[h][3], a, b1[2], b1[3]);
          mma_16816(accI[h][4], a, b2[0], b2[1]);
          mma_16816(accI[h][5], a, b3[0], b3[1]);
          mma_16816(accI[h][6], a, b2[2], b2[3]);
          mma_16816(accI[h][7], a, b3[2], b3[3]);
        }
      }
      bar_sync(1, NTH);
      bar_sync(2, NTH);

      // read REC dump (identical cell layout) and run epilogue
      float garr[64];
      #pragma unroll
      for (int i = 0; i < 16; i++)
        lds128(gsrc + (unsigned)(i*16), garr[4*i], garr[4*i+1], garr[4*i+2], garr[4*i+3]);

      __half* hslot = d_hring + hring_off(l, (t+1)&3, 0, 0);
      #pragma unroll
      for (int mt = 0; mt < 2; mt++)
        #pragma unroll
        for (int rr = 0; rr < 2; rr++){
          int row = wi*32 + mt*16 + gid + rr*8;
          #pragma unroll
          for (int jh = 0; jh < 2; jh++){
            float hv[2];
            #pragma unroll
            for (int cc = 0; cc < 2; cc++){
              int e  = rr*2 + cc;
              int ci = mt*8 + rr*4 + jh*2 + cc;
              float gi = accI[mt][jh  ][e] + garr[(mt*8 + jh  )*4 + e] + bias[     jh*2 + cc];
              float gf = accI[mt][2+jh][e] + garr[(mt*8 + 2+jh)*4 + e] + bias[ 4 + jh*2 + cc];
              float gg = accI[mt][4+jh][e] + garr[(mt*8 + 4+jh)*4 + e] + bias[ 8 + jh*2 + cc];
              float go = accI[mt][6+jh][e] + garr[(mt*8 + 6+jh)*4 + e] + bias[12 + jh*2 + cc];
              float c  = sig_fast(gf)*creg[ci] + sig_fast(gi)*tanh_fast(gg);
              creg[ci] = c;
              hv[cc]   = sig_fast(go)*tanh_fast(c);
            }
            int col0 = cid*16 + jh*8 + ct*2;
            __half2 h2 = __floats2half2_rn(hv[0], hv[1]);
            st_cg_u32(hslot + row*HH + col0, *(unsigned*)&h2);
            if (t == TT-1){
              out[(l*BB + row)*HH + col0    ] = hv[0];
              out[(l*BB + row)*HH + col0 + 1] = hv[1];
            }
          }
        }
      bar_sync(3, 128);
      if (tid == 128) arrive_release(&g_arrive[l]);
    }
  }
}

__global__ void __launch_bounds__(NTH, 1)
lstm_persist(const float* __restrict__ c0, float* __restrict__ out)
{
  extern __shared__ __align__(16) char smem_raw[];
  const int l = blockIdx.x >> 4, cid = blockIdx.x & 15;
  if (l == 0) run_layer<INW>(0, cid, c0, out, smem_raw);
  else        run_layer<HH >(l, cid, c0, out, smem_raw);
}

// ---------------- launch ----------------
extern "C" void kernel_launch(void* const* d_in, const int* in_sizes, int n_in,
                              void* d_out, int out_size){
  const float* x     = (const float*)d_in[0];
  const float* h0    = (const float*)d_in[1];
  const float* c0    = (const float*)d_in[2];
  const float* w_ih0 = (const float*)d_in[3];
  const float* w_ih  = (const float*)d_in[4];
  const float* w_hh  = (const float*)d_in[5];
  const float* b_ih  = (const float*)d_in[6];
  const float* b_hh  = (const float*)d_in[7];
  float* out = (float*)d_out;

  cudaFuncSetAttribute(lstm_persist, cudaFuncAttributeMaxDynamicSharedMemorySize, SMEM_BYTES);

  prep_pack<<<(LL*FOURH*KMAX + 255)/256, 256>>>(w_ih0, w_ih, w_hh, b_ih, b_hh);
  prep_x   <<<(BB*TT*INW    + 255)/256, 256>>>(x);
  prep_init<<<(LL*BB*HH     + 255)/256, 256>>>(h0);
  lstm_persist<<<GRIDB, NTH, SMEM_BYTES>>>(c0, out);
}

// round 9
// speedup vs baseline: 1.3688x; 1.1540x over previous
#include <cuda_runtime.h>
#include <cuda_fp16.h>
#include <stdint.h>

#define BB    128
#define TT    512
#define HH    256
#define LL    6
#define INW   128
#define FOURH 1024
#define NC    16
#define GRIDB (LL*NC)      // 96
#define NTH   256
#define KMAX  512
#define SIWC  (KMAX + 8)   // 520 halfs row stride (weights AND A tile)
#define GSTR  144          // per-thread gbuf slot stride in BYTES (36 words, 16B-aligned)
// ws 64*520*2 + A 128*520*2 + gbuf 128*144 = 66560 + 133120 + 18432 = 218112
#define SMEM_BYTES (64*SIWC*2 + 128*SIWC*2 + 128*GSTR)

// ---------------- persistent device state ----------------
__device__ __align__(256) __half d_wpack[(size_t)LL*FOURH*KMAX];  // rows: [Whh(256) | Wih(din)]
__device__ __align__(256) float  d_bpack[LL*FOURH];
__device__ __align__(256) __half d_xh[(size_t)BB*TT*INW];
__device__ __align__(256) __half d_hring[LL*4*BB*HH];             // 4-slot h ring per layer
__device__ unsigned g_arrive[LL];

__device__ __forceinline__ int hring_off(int l, int slot, int b, int k){
  return ((l*4 + slot)*BB + b)*HH + k;
}

// ---------------- prep kernels ----------------
// Packed row p in 64-row CTA chunk: p = gate*16 + jj. Cols: [0,256)=Whh, [256,256+din)=Wih.
__global__ void prep_pack(const float* __restrict__ w_ih0,
                          const float* __restrict__ w_ih,
                          const float* __restrict__ w_hh,
                          const float* __restrict__ b_ih,
                          const float* __restrict__ b_hh){
  long long idx = (long long)blockIdx.x*blockDim.x + threadIdx.x;
  if (idx >= (long long)LL*FOURH*KMAX) return;
  int k = (int)(idx % KMAX);
  int p = (int)((idx / KMAX) % FOURH);
  int l = (int)(idx / ((long long)KMAX*FOURH));
  int cid = p >> 6, rr = p & 63, gate = rr >> 4, jj = rr & 15;
  int srow = gate*HH + cid*16 + jj;
  int din  = (l == 0) ? INW : HH;
  float v = 0.f;
  if (k < HH)             v = w_hh[((size_t)l*FOURH + srow)*HH + k];
  else if (k < HH + din)  v = (l == 0) ? w_ih0[srow*INW + (k - HH)]
                                       : w_ih[((size_t)(l-1)*FOURH + srow)*HH + (k - HH)];
  d_wpack[idx] = __float2half(v);
  if (k == 0) d_bpack[l*FOURH + p] = b_ih[l*FOURH + srow] + b_hh[l*FOURH + srow];
}

__global__ void prep_x(const float* __restrict__ x){
  long long i = (long long)blockIdx.x*blockDim.x + threadIdx.x;
  if (i < (long long)BB*TT*INW) d_xh[i] = __float2half(x[i]);
}

__global__ void prep_init(const float* __restrict__ h0){
  int i = blockIdx.x*blockDim.x + threadIdx.x;
  if (i < LL*BB*HH){
    int l = i/(BB*HH), rem = i%(BB*HH);
    d_hring[hring_off(l, 0, rem/HH, rem%HH)] = __float2half(h0[i]);
  }
  if (i == 0){
    #pragma unroll
    for (int l = 0; l < LL; l++) g_arrive[l] = 0u;
  }
}

// ---------------- low-level helpers ----------------
__device__ __forceinline__ unsigned smem_u32(const void* p){
  unsigned a;
  asm("{ .reg .u64 t; cvta.to.shared.u64 t, %1; cvt.u32.u64 %0, t; }" : "=r"(a) : "l"(p));
  return a;
}
__device__ __forceinline__ void cp_async16(uint32_t dst, const void* src){
  asm volatile("cp.async.cg.shared.global [%0], [%1], 16;" :: "r"(dst), "l"(src));
}
__device__ __forceinline__ void bar_sync(int id, int cnt){
  asm volatile("bar.sync %0, %1;" :: "r"(id), "r"(cnt) : "memory");
}
__device__ __forceinline__ void ldsm_x4(unsigned addr, unsigned& r0, unsigned& r1,
                                        unsigned& r2, unsigned& r3){
  asm volatile("ldmatrix.sync.aligned.m8n8.x4.shared.b16 {%0,%1,%2,%3}, [%4];\n"
               : "=r"(r0), "=r"(r1), "=r"(r2), "=r"(r3) : "r"(addr));
}
__device__ __forceinline__ void mma_16816(float d[4], const unsigned a[4], const unsigned b0,
                                          const unsigned b1){
  asm volatile("mma.sync.aligned.m16n8k16.row.col.f32.f16.f16.f32 "
               "{%0,%1,%2,%3}, {%4,%5,%6,%7}, {%8,%9}, {%0,%1,%2,%3};\n"
               : "+f"(d[0]), "+f"(d[1]), "+f"(d[2]), "+f"(d[3])
               : "r"(a[0]), "r"(a[1]), "r"(a[2]), "r"(a[3]), "r"(b0), "r"(b1));
}
__device__ __forceinline__ float tanh_fast(float x){
  float r; asm("tanh.approx.f32 %0, %1;" : "=f"(r) : "f"(x)); return r;
}
__device__ __forceinline__ float sig_fast(float x){
  return fmaf(tanh_fast(0.5f*x), 0.5f, 0.5f);
}
__device__ __forceinline__ void wait_ge(unsigned* p, unsigned target){
  unsigned v;
  #pragma unroll 1
  do {
    asm volatile("ld.acquire.gpu.global.u32 %0, [%1];" : "=r"(v) : "l"(p) : "memory");
  } while (v < target);
}
__device__ __forceinline__ void arrive_release(unsigned* p){
  asm volatile("red.release.gpu.global.add.u32 [%0], %1;" :: "l"(p), "r"(1u) : "memory");
}
__device__ __forceinline__ void st_cg_u32(void* p, unsigned v){
  asm volatile("st.global.cg.u32 [%0], %1;" :: "l"(p), "r"(v) : "memory");
}
__device__ __forceinline__ void sts128(uint32_t addr, unsigned a, unsigned b,
                                       unsigned c, unsigned d){
  asm volatile("st.shared.v4.b32 [%0], {%1,%2,%3,%4};"
               :: "r"(addr), "r"(a), "r"(b), "r"(c), "r"(d) : "memory");
}
__device__ __forceinline__ void lds128(uint32_t addr, unsigned& a, unsigned& b,
                                       unsigned& c, unsigned& d){
  asm volatile("ld.shared.v4.b32 {%0,%1,%2,%3}, [%4];"
               : "=r"(a), "=r"(b), "=r"(c), "=r"(d) : "r"(addr));
}
__device__ __forceinline__ unsigned pack2(float a, float b){
  __half2 h = __floats2half2_rn(a, b);
  return *(unsigned*)&h;
}

// ---------------- per-layer persistent worker ----------------
// Unified A tile [128][520]: cols [0,256) = own h_{t-1} (REC stages+reads),
// cols [256,512) = input from below (INP stages+reads). Column-disjoint, so
// REC and INP phases never race on A. gbuf (fp16) hands REC's raw accumulators
// to INP, which owns the gate epilogue and cell state.
template<int DINA>
__device__ __forceinline__ void run_layer(const int l, const int cid,
                                          const float* __restrict__ c0,
                                          float* __restrict__ out, char* smem_raw)
{
  constexpr int SIW = SIWC;
  constexpr int NI  = DINA/16;               // input k16 iters
  constexpr int CHI = DINA/8;                // input 16B chunks per row
  __half* ws = (__half*)smem_raw;            // [64][520]
  __half* A  = ws + 64*SIW;                  // [128][520]
  uint32_t* gbuf = (uint32_t*)(A + 128*SIW); // 128 slots * GSTR bytes (fp16 pairs)
  const int tid = threadIdx.x;

  // ---- stage weights once (all 256 threads) ----
  {
    const __half* src = d_wpack + ((size_t)(l*FOURH + cid*64))*KMAX;
    for (int v = tid; v < 64*64; v += NTH){
      int r = v >> 6, kk = (v & 63)*8;
      *(uint4*)(ws + r*SIW + kk) = *(const uint4*)(src + (size_t)r*KMAX + kk);
    }
  }

  const int w = tid >> 5, lane = tid & 31;
  const int q = lane >> 3, rs = lane & 7;
  const int gid = lane >> 2, ct = lane & 3;

  // B fragment bases (Whh cols [0,256)); +512B for Wih cols [256,...)
  unsigned bX[4];
  {
    const int Xs[4] = {0, 8, 32, 40};
    #pragma unroll
    for (int i = 0; i < 4; i++)
      bX[i] = smem_u32(ws + (Xs[i] + rs + ((q>>1)<<4))*SIW + ((q&1)<<3));
  }
  const uint32_t Abase = smem_u32(A);

  __syncthreads();

  if (w < 4){
    // ================= REC warps: critical path =================
    const unsigned aB0 = smem_u32(A + (w*32 + rs + ((q&1)<<3))*SIW + ((q>>1)<<3));
    const unsigned aB1 = aB0 + (unsigned)(32*SIW);      // +16 rows (bytes)
    const uint32_t gdst = smem_u32(gbuf) + (unsigned)tid*GSTR;

    for (int t = 0; t < TT; t++){
      if (tid == 0){
        if (t > 0)               wait_ge(&g_arrive[l],   16u*(unsigned)t);
        if (l < LL-1 && t >= 3)  wait_ge(&g_arrive[l+1], 16u*(unsigned)(t-2));
      }
      bar_sync(4, 128);

      // stage own h_{t-1} (slot t&3) into A cols [0,256), two K-half groups
      const __half* hs = d_hring + hring_off(l, t&3, 0, 0);
      for (int v = tid; v < 2048; v += 128){
        int r = v >> 4, c = (v & 15)*8;
        cp_async16(Abase + (uint32_t)(r*SIW + c)*2u, hs + r*HH + c);
      }
      asm volatile("cp.async.commit_group;");
      for (int v = tid; v < 2048; v += 128){
        int r = v >> 4, c = 128 + (v & 15)*8;
        cp_async16(Abase + (uint32_t)(r*SIW + c)*2u, hs + r*HH + c);
      }
      asm volatile("cp.async.commit_group;");

      float acc[2][8][4];
      #pragma unroll
      for (int i = 0; i < 2; i++)
        #pragma unroll
        for (int j = 0; j < 8; j++)
          #pragma unroll
          for (int e = 0; e < 4; e++) acc[i][j][e] = 0.f;

      asm volatile("cp.async.wait_group 1;" ::: "memory");
      bar_sync(5, 128);
      #pragma unroll
      for (int ki = 0; ki < 8; ki++){
        const unsigned kofs = (unsigned)(ki*32);
        unsigned a0[4], a1[4], b0[4], b1[4], b2[4], b3[4];
        ldsm_x4(aB0 + kofs, a0[0], a0[1], a0[2], a0[3]);
        ldsm_x4(aB1 + kofs, a1[0], a1[1], a1[2], a1[3]);
        ldsm_x4(bX[0] + kofs, b0[0], b0[1], b0[2], b0[3]);
        ldsm_x4(bX[1] + kofs, b1[0], b1[1], b1[2], b1[3]);
        ldsm_x4(bX[2] + kofs, b2[0], b2[1], b2[2], b2[3]);
        ldsm_x4(bX[3] + kofs, b3[0], b3[1], b3[2], b3[3]);
        #pragma unroll
        for (int mt = 0; mt < 2; mt++){
          const unsigned* a = mt ? a1 : a0;
          mma_16816(acc[mt][0], a, b0[0], b0[1]);
          mma_16816(acc[mt][1], a, b1[0], b1[1]);
          mma_16816(acc[mt][2], a, b0[2], b0[3]);
          mma_16816(acc[mt][3], a, b1[2], b1[3]);
          mma_16816(acc[mt][4], a, b2[0], b2[1]);
          mma_16816(acc[mt][5], a, b3[0], b3[1]);
          mma_16816(acc[mt][6], a, b2[2], b2[3]);
          mma_16816(acc[mt][7], a, b3[2], b3[3]);
        }
      }
      asm volatile("cp.async.wait_group 0;" ::: "memory");
      bar_sync(4, 128);
      #pragma unroll
      for (int ki = 8; ki < 16; ki++){
        const unsigned kofs = (unsigned)(ki*32);
        unsigned a0[4], a1[4], b0[4], b1[4], b2[4], b3[4];
        ldsm_x4(aB0 + kofs, a0[0], a0[1], a0[2], a0[3]);
        ldsm_x4(aB1 + kofs, a1[0], a1[1], a1[2], a1[3]);
        ldsm_x4(bX[0] + kofs, b0[0], b0[1], b0[2], b0[3]);
        ldsm_x4(bX[1] + kofs, b1[0], b1[1], b1[2], b1[3]);
        ldsm_x4(bX[2] + kofs, b2[0], b2[1], b2[2], b2[3]);
        ldsm_x4(bX[3] + kofs, b3[0], b3[1], b3[2], b3[3]);
        #pragma unroll
        for (int mt = 0; mt < 2; mt++){
          const unsigned* a = mt ? a1 : a0;
          mma_16816(acc[mt][0], a, b0[0], b0[1]);
          mma_16816(acc[mt][1], a, b1[0], b1[1]);
          mma_16816(acc[mt][2], a, b0[2], b0[3]);
          mma_16816(acc[mt][3], a, b1[2], b1[3]);
          mma_16816(acc[mt][4], a, b2[0], b2[1]);
          mma_16816(acc[mt][5], a, b3[0], b3[1]);
          mma_16816(acc[mt][6], a, b2[2], b2[3]);
          mma_16816(acc[mt][7], a, b3[2], b3[3]);
        }
      }
      bar_sync(1, NTH);
      // dump as fp16 pairs: tile j = mt*8+nt -> words 2j, 2j+1
      #pragma unroll
      for (int i = 0; i < 8; i++){
        const int j0 = 2*i, j1 = 2*i + 1;
        const float* t0 = acc[j0 >> 3][j0 & 7];
        const float* t1 = acc[j1 >> 3][j1 & 7];
        sts128(gdst + (unsigned)(i*16),
               pack2(t0[0], t0[1]), pack2(t0[2], t0[3]),
               pack2(t1[0], t1[1]), pack2(t1[2], t1[3]));
      }
      bar_sync(2, NTH);
    }
  } else {
    // ================= INP warps: input GEMM + epilogue =================
    const int wi = w - 4;
    const unsigned aI0 = smem_u32(A + (wi*32 + rs + ((q&1)<<3))*SIW + 256 + ((q>>1)<<3));
    const unsigned aI1 = aI0 + (unsigned)(32*SIW);
    unsigned bI[4];
    #pragma unroll
    for (int i = 0; i < 4; i++) bI[i] = bX[i] + 512u;
    const uint32_t gsrc = smem_u32(gbuf) + (unsigned)(tid - 128)*GSTR;

    float bias[16];
    #pragma unroll
    for (int g = 0; g < 4; g++)
      #pragma unroll
      for (int jh = 0; jh < 2; jh++)
        #pragma unroll
        for (int cc = 0; cc < 2; cc++)
          bias[g*4 + jh*2 + cc] = d_bpack[l*FOURH + cid*64 + g*16 + jh*8 + ct*2 + cc];

    float creg[16];
    #pragma unroll
    for (int mt = 0; mt < 2; mt++)
      #pragma unroll
      for (int rr = 0; rr < 2; rr++)
        #pragma unroll
        for (int jh = 0; jh < 2; jh++)
          #pragma unroll
          for (int cc = 0; cc < 2; cc++){
            int row = wi*32 + mt*16 + gid + rr*8;
            int col = cid*16 + jh*8 + ct*2 + cc;
            creg[mt*8 + rr*4 + jh*2 + cc] = c0[(l*BB + row)*HH + col];
          }

    // stage input(tt) into A cols [256, 256+DINA)
    auto stage_input = [&](int tt){
      for (int v = tid - 128; v < 128*CHI; v += 128){
        int r = v / CHI, kk = (v - r*CHI)*8;
        const __half* src = (DINA == INW)
          ? d_xh + ((size_t)r*TT + tt)*INW + kk
          : d_hring + hring_off(l-1, (tt+1)&3, r, kk);
        cp_async16(Abase + (uint32_t)(r*SIW + 256 + kk)*2u, src);
      }
      asm volatile("cp.async.commit_group;");
      asm volatile("cp.async.wait_group 0;" ::: "memory");
    };

    // preamble: input(0)
    if (tid == 128 && l > 0) wait_ge(&g_arrive[l-1], 16u);
    bar_sync(3, 128);
    stage_input(0);
    bar_sync(3, 128);

    for (int t = 0; t < TT; t++){
      // input GEMM K=DINA -> accI
      float accI[2][8][4];
      #pragma unroll
      for (int i = 0; i < 2; i++)
        #pragma unroll
        for (int j = 0; j < 8; j++)
          #pragma unroll
          for (int e = 0; e < 4; e++) accI[i][j][e] = 0.f;
      #pragma unroll
      for (int ki = 0; ki < NI; ki++){
        const unsigned kofs = (unsigned)(ki*32);
        unsigned a0[4], a1[4], b0[4], b1[4], b2[4], b3[4];
        ldsm_x4(aI0 + kofs, a0[0], a0[1], a0[2], a0[3]);
        ldsm_x4(aI1 + kofs, a1[0], a1[1], a1[2], a1[3]);
        ldsm_x4(bI[0] + kofs, b0[0], b0[1], b0[2], b0[3]);
        ldsm_x4(bI[1] + kofs, b1[0], b1[1], b1[2], b1[3]);
        ldsm_x4(bI[2] + kofs, b2[0], b2[1], b2[2], b2[3]);
        ldsm_x4(bI[3] + kofs, b3[0], b3[1], b3[2], b3[3]);
        #pragma unroll
        for (int mt = 0; mt < 2; mt++){
          const unsigned* a = mt ? a1 : a0;
          mma_16816(accI[mt][0], a, b0[0], b0[1]);
          mma_16816(accI[mt][1], a, b1[0], b1[1]);
          mma_16816(accI[mt][2], a, b0[2], b0[3]);
          mma_16816(accI[mt][3], a, b1[2], b1[3]);
          mma_16816(accI[mt][4], a, b2[0], b2[1]);
          mma_16816(accI[mt][5], a, b3[0], b3[1]);
          mma_16816(accI[mt][6], a, b2[2], b2[3]);
          mma_16816(accI[mt][7], a, b3[2], b3[3]);
        }
      }
      bar_sync(1, NTH);
      bar_sync(2, NTH);

      // read REC dump (fp16 pairs, identical cell layout)
      unsigned g32[32];
      #pragma unroll
      for (int i = 0; i < 8; i++)
        lds128(gsrc + (unsigned)(i*16), g32[4*i], g32[4*i+1], g32[4*i+2], g32[4*i+3]);

      __half* hslot = d_hring + hring_off(l, (t+1)&3, 0, 0);
      #pragma unroll
      for (int mt = 0; mt < 2; mt++)
        #pragma unroll
        for (int rr = 0; rr < 2; rr++){
          int row = wi*32 + mt*16 + gid + rr*8;
          #pragma unroll
          for (int jh = 0; jh < 2; jh++){
            // gate G tile j = mt*8 + G*2 + jh ; word 2j + rr ; half = cc
            float2 gI = __half22float2(*(const __half2*)&g32[(mt*8 +      jh)*2 + rr]);
            float2 gF = __half22float2(*(const __half2*)&g32[(mt*8 + 2 + jh)*2 + rr]);
            float2 gG = __half22float2(*(const __half2*)&g32[(mt*8 + 4 + jh)*2 + rr]);
            float2 gO = __half22float2(*(const __half2*)&g32[(mt*8 + 6 + jh)*2 + rr]);
            float hv[2];
            #pragma unroll
            for (int cc = 0; cc < 2; cc++){
              int e  = rr*2 + cc;
              int ci = mt*8 + rr*4 + jh*2 + cc;
              float gi = accI[mt][     jh][e] + (cc ? gI.y : gI.x) + bias[     jh*2 + cc];
              float gf = accI[mt][2 + jh][e] + (cc ? gF.y : gF.x) + bias[ 4 + jh*2 + cc];
              float gg = accI[mt][4 + jh][e] + (cc ? gG.y : gG.x) + bias[ 8 + jh*2 + cc];
              float go = accI[mt][6 + jh][e] + (cc ? gO.y : gO.x) + bias[12 + jh*2 + cc];
              float c  = sig_fast(gf)*creg[ci] + sig_fast(gi)*tanh_fast(gg);
              creg[ci] = c;
              hv[cc]   = sig_fast(go)*tanh_fast(c);
            }
            int col0 = cid*16 + jh*8 + ct*2;
            st_cg_u32(hslot + row*HH + col0, pack2(hv[0], hv[1]));
            if (t == TT-1){
              out[(l*BB + row)*HH + col0    ] = hv[0];
              out[(l*BB + row)*HH + col0 + 1] = hv[1];
            }
          }
        }
      bar_sync(3, 128);
      if (tid == 128) arrive_release(&g_arrive[l]);

      // stage input(t+1) (off critical path; cols disjoint from REC's)
      if (t < TT-1){
        if (tid == 128 && l > 0) wait_ge(&g_arrive[l-1], 16u*(unsigned)(t+2));
        bar_sync(3, 128);
        stage_input(t+1);
        bar_sync(3, 128);
      }
    }
  }
}

__global__ void __launch_bounds__(NTH, 1)
lstm_persist(const float* __restrict__ c0, float* __restrict__ out)
{
  extern __shared__ __align__(16) char smem_raw[];
  const int l = blockIdx.x >> 4, cid = blockIdx.x & 15;
  if (l == 0) run_layer<INW>(0, cid, c0, out, smem_raw);
  else        run_layer<HH >(l, cid, c0, out, smem_raw);
}

// ---------------- launch ----------------
extern "C" void kernel_launch(void* const* d_in, const int* in_sizes, int n_in,
                              void* d_out, int out_size){
  const float* x     = (const float*)d_in[0];
  const float* h0    = (const float*)d_in[1];
  const float* c0    = (const float*)d_in[2];
  const float* w_ih0 = (const float*)d_in[3];
  const float* w_ih  = (const float*)d_in[4];
  const float* w_hh  = (const float*)d_in[5];
  const float* b_ih  = (const float*)d_in[6];
  const float* b_hh  = (const float*)d_in[7];
  float* out = (float*)d_out;

  cudaFuncSetAttribute(lstm_persist, cudaFuncAttributeMaxDynamicSharedMemorySize, SMEM_BYTES);

  prep_pack<<<(LL*FOURH*KMAX + 255)/256, 256>>>(w_ih0, w_ih, w_hh, b_ih, b_hh);
  prep_x   <<<(BB*TT*INW    + 255)/256, 256>>>(x);
  prep_init<<<(LL*BB*HH     + 255)/256, 256>>>(h0);
  lstm_persist<<<GRIDB, NTH, SMEM_BYTES>>>(c0, out);
}

// round 10
// speedup vs baseline: 1.6626x; 1.2147x over previous
#include <cuda_runtime.h>
#include <cuda_fp16.h>
#include <stdint.h>

#define BB    128
#define TT    512
#define HH    256
#define LL    6
#define INW   128
#define FOURH 1024
#define NC    16
#define GRIDB (LL*NC)      // 96
#define NTH   256
#define KMAX  512
#define SIWC  (KMAX + 8)   // 520 halfs row stride (weights AND A tile)
#define GSTR  144          // per-thread gbuf slot stride in BYTES (16B-aligned)
// ws 64*520*2 + A 128*520*2 + gbuf 128*144 = 218112
#define SMEM_BYTES (64*SIWC*2 + 128*SIWC*2 + 128*GSTR)

// ---------------- persistent device state ----------------
__device__ __align__(256) __half d_wpack[(size_t)LL*FOURH*KMAX];  // rows: [Whh(256) | Wih(din)]
__device__ __align__(256) float  d_bpack[LL*FOURH];
__device__ __align__(256) __half d_xh[(size_t)BB*TT*INW];
__device__ __align__(256) __half d_hring[LL*4*BB*HH];             // 4-slot h ring per layer
__device__ unsigned g_arrive[LL];

__device__ __forceinline__ int hring_off(int l, int slot, int b, int k){
  return ((l*4 + slot)*BB + b)*HH + k;
}

// ---------------- prep kernels ----------------
__global__ void prep_pack(const float* __restrict__ w_ih0,
                          const float* __restrict__ w_ih,
                          const float* __restrict__ w_hh,
                          const float* __restrict__ b_ih,
                          const float* __restrict__ b_hh){
  long long idx = (long long)blockIdx.x*blockDim.x + threadIdx.x;
  if (idx >= (long long)LL*FOURH*KMAX) return;
  int k = (int)(idx % KMAX);
  int p = (int)((idx / KMAX) % FOURH);
  int l = (int)(idx / ((long long)KMAX*FOURH));
  int cid = p >> 6, rr = p & 63, gate = rr >> 4, jj = rr & 15;
  int srow = gate*HH + cid*16 + jj;
  int din  = (l == 0) ? INW : HH;
  float v = 0.f;
  if (k < HH)             v = w_hh[((size_t)l*FOURH + srow)*HH + k];
  else if (k < HH + din)  v = (l == 0) ? w_ih0[srow*INW + (k - HH)]
                                       : w_ih[((size_t)(l-1)*FOURH + srow)*HH + (k - HH)];
  d_wpack[idx] = __float2half(v);
  if (k == 0) d_bpack[l*FOURH + p] = b_ih[l*FOURH + srow] + b_hh[l*FOURH + srow];
}

__global__ void prep_x(const float* __restrict__ x){
  long long i = (long long)blockIdx.x*blockDim.x + threadIdx.x;
  if (i < (long long)BB*TT*INW) d_xh[i] = __float2half(x[i]);
}

__global__ void prep_init(const float* __restrict__ h0){
  int i = blockIdx.x*blockDim.x + threadIdx.x;
  if (i < LL*BB*HH){
    int l = i/(BB*HH), rem = i%(BB*HH);
    d_hring[hring_off(l, 0, rem/HH, rem%HH)] = __float2half(h0[i]);
  }
  if (i == 0){
    #pragma unroll
    for (int l = 0; l < LL; l++) g_arrive[l] = 0u;
  }
}

// ---------------- low-level helpers ----------------
__device__ __forceinline__ unsigned smem_u32(const void* p){
  unsigned a;
  asm("{ .reg .u64 t; cvta.to.shared.u64 t, %1; cvt.u32.u64 %0, t; }" : "=r"(a) : "l"(p));
  return a;
}
__device__ __forceinline__ void cp_async16(uint32_t dst, const void* src){
  asm volatile("cp.async.cg.shared.global [%0], [%1], 16;" :: "r"(dst), "l"(src));
}
__device__ __forceinline__ void bar_sync(int id, int cnt){
  asm volatile("bar.sync %0, %1;" :: "r"(id), "r"(cnt) : "memory");
}
__device__ __forceinline__ void bar_arrive(int id, int cnt){
  asm volatile("bar.arrive %0, %1;" :: "r"(id), "r"(cnt) : "memory");
}
__device__ __forceinline__ void ldsm_x4(unsigned addr, unsigned& r0, unsigned& r1,
                                        unsigned& r2, unsigned& r3){
  asm volatile("ldmatrix.sync.aligned.m8n8.x4.shared.b16 {%0,%1,%2,%3}, [%4];\n"
               : "=r"(r0), "=r"(r1), "=r"(r2), "=r"(r3) : "r"(addr));
}
__device__ __forceinline__ void mma_16816(float d[4], const unsigned a[4], const unsigned b0,
                                          const unsigned b1){
  asm volatile("mma.sync.aligned.m16n8k16.row.col.f32.f16.f16.f32 "
               "{%0,%1,%2,%3}, {%4,%5,%6,%7}, {%8,%9}, {%0,%1,%2,%3};\n"
               : "+f"(d[0]), "+f"(d[1]), "+f"(d[2]), "+f"(d[3])
               : "r"(a[0]), "r"(a[1]), "r"(a[2]), "r"(a[3]), "r"(b0), "r"(b1));
}
__device__ __forceinline__ float tanh_fast(float x){
  float r; asm("tanh.approx.f32 %0, %1;" : "=f"(r) : "f"(x)); return r;
}
__device__ __forceinline__ float sig_fast(float x){
  return fmaf(tanh_fast(0.5f*x), 0.5f, 0.5f);
}
__device__ __forceinline__ void wait_ge(unsigned* p, unsigned target){
  unsigned v;
  #pragma unroll 1
  do {
    asm volatile("ld.acquire.gpu.global.u32 %0, [%1];" : "=r"(v) : "l"(p) : "memory");
  } while (v < target);
}
__device__ __forceinline__ void arrive_release(unsigned* p){
  asm volatile("red.release.gpu.global.add.u32 [%0], %1;" :: "l"(p), "r"(1u) : "memory");
}
__device__ __forceinline__ void st_cg_u32(void* p, unsigned v){
  asm volatile("st.global.cg.u32 [%0], %1;" :: "l"(p), "r"(v) : "memory");
}
__device__ __forceinline__ void sts128(uint32_t addr, unsigned a, unsigned b,
                                       unsigned c, unsigned d){
  asm volatile("st.shared.v4.b32 [%0], {%1,%2,%3,%4};"
               :: "r"(addr), "r"(a), "r"(b), "r"(c), "r"(d) : "memory");
}
__device__ __forceinline__ void lds128(uint32_t addr, unsigned& a, unsigned& b,
                                       unsigned& c, unsigned& d){
  asm volatile("ld.shared.v4.b32 {%0,%1,%2,%3}, [%4];"
               : "=r"(a), "=r"(b), "=r"(c), "=r"(d) : "r"(addr));
}
__device__ __forceinline__ unsigned pack2(float a, float b){
  __half2 h = __floats2half2_rn(a, b);
  return *(unsigned*)&h;
}

// ---------------- per-layer persistent worker ----------------
// REVERSED handoff vs R9: INP warps (4..7) stage+GEMM the input contribution
// and dump it (fp16) to gbuf DURING REC's recurrent GEMM; REC warps (0..3)
// consume the dump and run the gate epilogue themselves (creg lives in REC).
// bar1: INP arrive (dump ready) / REC sync. bar2: REC arrive (dump consumed)
// / INP sync — WAR backpressure for the next dump.
template<int DINA>
__device__ __forceinline__ void run_layer(const int l, const int cid,
                                          const float* __restrict__ c0,
                                          float* __restrict__ out, char* smem_raw)
{
  constexpr int SIW = SIWC;
  constexpr int NI  = DINA/16;               // input k16 iters
  constexpr int CHI = DINA/8;                // input 16B chunks per row
  __half* ws = (__half*)smem_raw;            // [64][520]
  __half* A  = ws + 64*SIW;                  // [128][520]
  uint32_t* gbuf = (uint32_t*)(A + 128*SIW); // 128 slots * GSTR bytes
  const int tid = threadIdx.x;

  // ---- stage weights once (all 256 threads) ----
  {
    const __half* src = d_wpack + ((size_t)(l*FOURH + cid*64))*KMAX;
    for (int v = tid; v < 64*64; v += NTH){
      int r = v >> 6, kk = (v & 63)*8;
      *(uint4*)(ws + r*SIW + kk) = *(const uint4*)(src + (size_t)r*KMAX + kk);
    }
  }

  const int w = tid >> 5, lane = tid & 31;
  const int q = lane >> 3, rs = lane & 7;
  const int gid = lane >> 2, ct = lane & 3;

  unsigned bX[4];
  {
    const int Xs[4] = {0, 8, 32, 40};
    #pragma unroll
    for (int i = 0; i < 4; i++)
      bX[i] = smem_u32(ws + (Xs[i] + rs + ((q>>1)<<4))*SIW + ((q&1)<<3));
  }
  const uint32_t Abase = smem_u32(A);

  __syncthreads();

  if (w < 4){
    // ========== REC warps: critical path + epilogue ==========
    const unsigned aB0 = smem_u32(A + (w*32 + rs + ((q&1)<<3))*SIW + ((q>>1)<<3));
    const unsigned aB1 = aB0 + (unsigned)(32*SIW);
    const uint32_t gsrc = smem_u32(gbuf) + (unsigned)tid*GSTR;

    float bias[16];
    #pragma unroll
    for (int g = 0; g < 4; g++)
      #pragma unroll
      for (int jh = 0; jh < 2; jh++)
        #pragma unroll
        for (int cc = 0; cc < 2; cc++)
          bias[g*4 + jh*2 + cc] = d_bpack[l*FOURH + cid*64 + g*16 + jh*8 + ct*2 + cc];

    float creg[16];
    #pragma unroll
    for (int mt = 0; mt < 2; mt++)
      #pragma unroll
      for (int rr = 0; rr < 2; rr++)
        #pragma unroll
        for (int jh = 0; jh < 2; jh++)
          #pragma unroll
          for (int cc = 0; cc < 2; cc++){
            int row = w*32 + mt*16 + gid + rr*8;
            int col = cid*16 + jh*8 + ct*2 + cc;
            creg[mt*8 + rr*4 + jh*2 + cc] = c0[(l*BB + row)*HH + col];
          }

    for (int t = 0; t < TT; t++){
      if (tid == 0){
        if (t > 0)               wait_ge(&g_arrive[l],   16u*(unsigned)t);
        if (l < LL-1 && t >= 3)  wait_ge(&g_arrive[l+1], 16u*(unsigned)(t-2));
      }
      bar_sync(4, 128);

      // stage own h_{t-1} (slot t&3) into A cols [0,256), two K-half groups
      const __half* hs = d_hring + hring_off(l, t&3, 0, 0);
      for (int v = tid; v < 2048; v += 128){
        int r = v >> 4, c = (v & 15)*8;
        cp_async16(Abase + (uint32_t)(r*SIW + c)*2u, hs + r*HH + c);
      }
      asm volatile("cp.async.commit_group;");
      for (int v = tid; v < 2048; v += 128){
        int r = v >> 4, c = 128 + (v & 15)*8;
        cp_async16(Abase + (uint32_t)(r*SIW + c)*2u, hs + r*HH + c);
      }
      asm volatile("cp.async.commit_group;");

      float acc[2][8][4];
      #pragma unroll
      for (int i = 0; i < 2; i++)
        #pragma unroll
        for (int j = 0; j < 8; j++)
          #pragma unroll
          for (int e = 0; e < 4; e++) acc[i][j][e] = 0.f;

      asm volatile("cp.async.wait_group 1;" ::: "memory");
      bar_sync(5, 128);
      #pragma unroll
      for (int ki = 0; ki < 8; ki++){
        const unsigned kofs = (unsigned)(ki*32);
        unsigned a0[4], a1[4], b0[4], b1[4], b2[4], b3[4];
        ldsm_x4(aB0 + kofs, a0[0], a0[1], a0[2], a0[3]);
        ldsm_x4(aB1 + kofs, a1[0], a1[1], a1[2], a1[3]);
        ldsm_x4(bX[0] + kofs, b0[0], b0[1], b0[2], b0[3]);
        ldsm_x4(bX[1] + kofs, b1[0], b1[1], b1[2], b1[3]);
        ldsm_x4(bX[2] + kofs, b2[0], b2[1], b2[2], b2[3]);
        ldsm_x4(bX[3] + kofs, b3[0], b3[1], b3[2], b3[3]);
        #pragma unroll
        for (int mt = 0; mt < 2; mt++){
          const unsigned* a = mt ? a1 : a0;
          mma_16816(acc[mt][0], a, b0[0], b0[1]);
          mma_16816(acc[mt][1], a, b1[0], b1[1]);
          mma_16816(acc[mt][2], a, b0[2], b0[3]);
          mma_16816(acc[mt][3], a, b1[2], b1[3]);
          mma_16816(acc[mt][4], a, b2[0], b2[1]);
          mma_16816(acc[mt][5], a, b3[0], b3[1]);
          mma_16816(acc[mt][6], a, b2[2], b2[3]);
          mma_16816(acc[mt][7], a, b3[2], b3[3]);
        }
      }
      asm volatile("cp.async.wait_group 0;" ::: "memory");
      bar_sync(4, 128);
      #pragma unroll
      for (int ki = 8; ki < 16; ki++){
        const unsigned kofs = (unsigned)(ki*32);
        unsigned a0[4], a1[4], b0[4], b1[4], b2[4], b3[4];
        ldsm_x4(aB0 + kofs, a0[0], a0[1], a0[2], a0[3]);
        ldsm_x4(aB1 + kofs, a1[0], a1[1], a1[2], a1[3]);
        ldsm_x4(bX[0] + kofs, b0[0], b0[1], b0[2], b0[3]);
        ldsm_x4(bX[1] + kofs, b1[0], b1[1], b1[2], b1[3]);
        ldsm_x4(bX[2] + kofs, b2[0], b2[1], b2[2], b2[3]);
        ldsm_x4(bX[3] + kofs, b3[0], b3[1], b3[2], b3[3]);
        #pragma unroll
        for (int mt = 0; mt < 2; mt++){
          const unsigned* a = mt ? a1 : a0;
          mma_16816(acc[mt][0], a, b0[0], b0[1]);
          mma_16816(acc[mt][1], a, b1[0], b1[1]);
          mma_16816(acc[mt][2], a, b0[2], b0[3]);
          mma_16816(acc[mt][3], a, b1[2], b1[3]);
          mma_16816(acc[mt][4], a, b2[0], b2[1]);
          mma_16816(acc[mt][5], a, b3[0], b3[1]);
          mma_16816(acc[mt][6], a, b2[2], b2[3]);
          mma_16816(acc[mt][7], a, b3[2], b3[3]);
        }
      }

      // consume INP dump (posted during our GEMM)
      bar_sync(1, NTH);
      unsigned g32[32];
      #pragma unroll
      for (int i = 0; i < 8; i++)
        lds128(gsrc + (unsigned)(i*16), g32[4*i], g32[4*i+1], g32[4*i+2], g32[4*i+3]);
      bar_arrive(2, NTH);

      // epilogue: gates = acc (recurrent fp32) + g32 (input fp16) + bias
      __half* hslot = d_hring + hring_off(l, (t+1)&3, 0, 0);
      #pragma unroll
      for (int mt = 0; mt < 2; mt++)
        #pragma unroll
        for (int rr = 0; rr < 2; rr++){
          int row = w*32 + mt*16 + gid + rr*8;
          #pragma unroll
          for (int jh = 0; jh < 2; jh++){
            float2 gI = __half22float2(*(const __half2*)&g32[(mt*8 +      jh)*2 + rr]);
            float2 gF = __half22float2(*(const __half2*)&g32[(mt*8 + 2 + jh)*2 + rr]);
            float2 gG = __half22float2(*(const __half2*)&g32[(mt*8 + 4 + jh)*2 + rr]);
            float2 gO = __half22float2(*(const __half2*)&g32[(mt*8 + 6 + jh)*2 + rr]);
            float hv[2];
            #pragma unroll
            for (int cc = 0; cc < 2; cc++){
              int e  = rr*2 + cc;
              int ci = mt*8 + rr*4 + jh*2 + cc;
              float gi = acc[mt][     jh][e] + (cc ? gI.y : gI.x) + bias[     jh*2 + cc];
              float gf = acc[mt][2 + jh][e] + (cc ? gF.y : gF.x) + bias[ 4 + jh*2 + cc];
              float gg = acc[mt][4 + jh][e] + (cc ? gG.y : gG.x) + bias[ 8 + jh*2 + cc];
              float go = acc[mt][6 + jh][e] + (cc ? gO.y : gO.x) + bias[12 + jh*2 + cc];
              float c  = sig_fast(gf)*creg[ci] + sig_fast(gi)*tanh_fast(gg);
              creg[ci] = c;
              hv[cc]   = sig_fast(go)*tanh_fast(c);
            }
            int col0 = cid*16 + jh*8 + ct*2;
            st_cg_u32(hslot + row*HH + col0, pack2(hv[0], hv[1]));
            if (t == TT-1){
              out[(l*BB + row)*HH + col0    ] = hv[0];
              out[(l*BB + row)*HH + col0 + 1] = hv[1];
            }
          }
        }
      bar_sync(4, 128);
      if (tid == 0) arrive_release(&g_arrive[l]);
    }
  } else {
    // ========== INP warps: input stage + GEMM + dump (off critical path) ==========
    const int wi = w - 4;
    const unsigned aI0 = smem_u32(A + (wi*32 + rs + ((q&1)<<3))*SIW + 256 + ((q>>1)<<3));
    const unsigned aI1 = aI0 + (unsigned)(32*SIW);
    unsigned bI[4];
    #pragma unroll
    for (int i = 0; i < 4; i++) bI[i] = bX[i] + 512u;
    const uint32_t gdst = smem_u32(gbuf) + (unsigned)(tid - 128)*GSTR;

    auto stage_input = [&](int tt){
      for (int v = tid - 128; v < 128*CHI; v += 128){
        int r = v / CHI, kk = (v - r*CHI)*8;
        const __half* src = (DINA == INW)
          ? d_xh + ((size_t)r*TT + tt)*INW + kk
          : d_hring + hring_off(l-1, (tt+1)&3, r, kk);
        cp_async16(Abase + (uint32_t)(r*SIW + 256 + kk)*2u, src);
      }
      asm volatile("cp.async.commit_group;");
      asm volatile("cp.async.wait_group 0;" ::: "memory");
    };

    if (tid == 128 && l > 0) wait_ge(&g_arrive[l-1], 16u);
    bar_sync(3, 128);
    stage_input(0);
    bar_sync(3, 128);

    for (int t = 0; t < TT; t++){
      float accI[2][8][4];
      #pragma unroll
      for (int i = 0; i < 2; i++)
        #pragma unroll
        for (int j = 0; j < 8; j++)
          #pragma unroll
          for (int e = 0; e < 4; e++) accI[i][j][e] = 0.f;
      #pragma unroll
      for (int ki = 0; ki < NI; ki++){
        const unsigned kofs = (unsigned)(ki*32);
        unsigned a0[4], a1[4], b0[4], b1[4], b2[4], b3[4];
        ldsm_x4(aI0 + kofs, a0[0], a0[1], a0[2], a0[3]);
        ldsm_x4(aI1 + kofs, a1[0], a1[1], a1[2], a1[3]);
        ldsm_x4(bI[0] + kofs, b0[0], b0[1], b0[2], b0[3]);
        ldsm_x4(bI[1] + kofs, b1[0], b1[1], b1[2], b1[3]);
        ldsm_x4(bI[2] + kofs, b2[0], b2[1], b2[2], b2[3]);
        ldsm_x4(bI[3] + kofs, b3[0], b3[1], b3[2], b3[3]);
        #pragma unroll
        for (int mt = 0; mt < 2; mt++){
          const unsigned* a = mt ? a1 : a0;
          mma_16816(accI[mt][0], a, b0[0], b0[1]);
          mma_16816(accI[mt][1], a, b1[0], b1[1]);
          mma_16816(accI[mt][2], a, b0[2], b0[3]);
          mma_16816(accI[mt][3], a, b1[2], b1[3]);
          mma_16816(accI[mt][4], a, b2[0], b2[1]);
          mma_16816(accI[mt][5], a, b3[0], b3[1]);
          mma_16816(accI[mt][6], a, b2[2], b2[3]);
          mma_16816(accI[mt][7], a, b3[2], b3[3]);
        }
      }

      if (t > 0) bar_sync(2, NTH);     // REC consumed dump(t-1)
      #pragma unroll
      for (int i = 0; i < 8; i++){
        const int j0 = 2*i, j1 = 2*i + 1;
        const float* t0 = accI[j0 >> 3][j0 & 7];
        const float* t1 = accI[j1 >> 3][j1 & 7];
        sts128(gdst + (unsigned)(i*16),
               pack2(t0[0], t0[1]), pack2(t0[2], t0[3]),
               pack2(t1[0], t1[1]), pack2(t1[2], t1[3]));
      }
      asm volatile("membar.cta;" ::: "memory");
      bar_arrive(1, NTH);              // dump(t) ready; REC consumes

      if (t < TT-1){
        if (tid == 128 && l > 0) wait_ge(&g_arrive[l-1], 16u*(unsigned)(t+2));
        bar_sync(3, 128);
        stage_input(t+1);
        bar_sync(3, 128);
      }
    }
  }
}

__global__ void __launch_bounds__(NTH, 1)
lstm_persist(const float* __restrict__ c0, float* __restrict__ out)
{
  extern __shared__ __align__(16) char smem_raw[];
  const int l = blockIdx.x >> 4, cid = blockIdx.x & 15;
  if (l == 0) run_layer<INW>(0, cid, c0, out, smem_raw);
  else        run_layer<HH >(l, cid, c0, out, smem_raw);
}

// ---------------- launch ----------------
extern "C" void kernel_launch(void* const* d_in, const int* in_sizes, int n_in,
                              void* d_out, int out_size){
  const float* x     = (const float*)d_in[0];
  const float* h0    = (const float*)d_in[1];
  const float* c0    = (const float*)d_in[2];
  const float* w_ih0 = (const float*)d_in[3];
  const float* w_ih  = (const float*)d_in[4];
  const float* w_hh  = (const float*)d_in[5];
  const float* b_ih  = (const float*)d_in[6];
  const float* b_hh  = (const float*)d_in[7];
  float* out = (float*)d_out;

  cudaFuncSetAttribute(lstm_persist, cudaFuncAttributeMaxDynamicSharedMemorySize, SMEM_BYTES);

  prep_pack<<<(LL*FOURH*KMAX + 255)/256, 256>>>(w_ih0, w_ih, w_hh, b_ih, b_hh);
  prep_x   <<<(BB*TT*INW    + 255)/256, 256>>>(x);
  prep_init<<<(LL*BB*HH     + 255)/256, 256>>>(h0);
  lstm_persist<<<GRIDB, NTH, SMEM_BYTES>>>(c0, out);
}